// round 1
// baseline (speedup 1.0000x reference)
#include <cuda_runtime.h>
#include <math.h>

#define LN_EPS 1e-5f

// ---------------- scratch (no allocation allowed) ----------------
struct Scratch {
    float t1[12288];          // gelu(conv1(x))
    float pos[12288];         // conv2(...)
    float patches[16 * 768];  // patch embed
    float qkvp[16 * 768];     // patch qkv
    float po[16 * 768];       // attn+proj output per token
    float comb[12288];        // out_patch then += out_seq
    float t2[12288];          // gelu(conv3(comb))
    float cden[20];           // moment-derived denominator coeffs
    float cnum[60];           // numerator coeffs (3 x 20)
    float A[72];              // per-head 3x3 score maps
    float C[72];              // per-head 3x3 value*proj maps
};
__device__ Scratch g_s;

// 1/(i! j! l!) for the 20 monomials of degree <= 3 (ordering below)
__device__ const float c_invfact[20] = {
    1.f, 1.f, 1.f, 1.f,
    0.5f, 1.f, 1.f, 0.5f, 1.f, 0.5f,
    1.f/6.f, 0.5f, 0.5f, 0.5f, 1.f, 0.5f, 1.f/6.f, 0.5f, 0.5f, 1.f/6.f
};
// index of monomial m (deg<=3) with exponent of variable c incremented (deg<=4 table)
__device__ const int c_plus[60] = {
    1,4,5,6,10,11,12,13,14,15,20,21,22,23,24,25,26,27,28,29,
    2,5,7,8,11,13,14,16,17,18,21,23,24,26,27,28,30,31,32,33,
    3,6,8,9,12,14,15,17,18,19,22,24,25,27,28,29,31,32,33,34
};

// monomials of (s0,s1,s2) up to degree 4, 35 values, ordering:
// deg0: ()  deg1: x,y,z  deg2: xx,xy,xz,yy,yz,zz
// deg3: xxx,xxy,xxz,xyy,xyz,xzz,yyy,yyz,yzz,zzz
// deg4: xxxx,xxxy,xxxz,xxyy,xxyz,xxzz,xyyy,xyyz,xyzz,xzzz,yyyy,yyyz,yyzz,yzzz,zzzz
__device__ __forceinline__ void mon35(float s0, float s1, float s2, float* m) {
    m[0]=1.f; m[1]=s0; m[2]=s1; m[3]=s2;
    m[4]=s0*s0; m[5]=s0*s1; m[6]=s0*s2; m[7]=s1*s1; m[8]=s1*s2; m[9]=s2*s2;
    m[10]=m[4]*s0; m[11]=m[4]*s1; m[12]=m[4]*s2; m[13]=s0*m[7]; m[14]=m[5]*s2;
    m[15]=s0*m[9]; m[16]=m[7]*s1; m[17]=m[7]*s2; m[18]=s1*m[9]; m[19]=m[9]*s2;
    m[20]=m[10]*s0; m[21]=m[10]*s1; m[22]=m[10]*s2; m[23]=m[11]*s1; m[24]=m[11]*s2;
    m[25]=m[12]*s2; m[26]=m[16]*s0; m[27]=m[13]*s2; m[28]=m[14]*s2; m[29]=m[19]*s0;
    m[30]=m[16]*s1; m[31]=m[16]*s2; m[32]=m[17]*s2; m[33]=m[19]*s1; m[34]=m[19]*s2;
}

// ---------------- 3x3 conv, pad 1, 3 channels in/out, optional exact gelu ----------------
__global__ void k_conv3(const float* __restrict__ in, const float* __restrict__ w,
                        float* __restrict__ out, int do_gelu) {
    int idx = blockIdx.x * blockDim.x + threadIdx.x;
    int o = idx >> 12, rem = idx & 4095, y = rem >> 6, x = rem & 63;
    float acc = 0.f;
    #pragma unroll
    for (int c = 0; c < 3; ++c) {
        const float* wp = w + (o * 3 + c) * 9;
        const float* ip = in + (c << 12);
        #pragma unroll
        for (int dy = 0; dy < 3; ++dy) {
            int yy = y + dy - 1;
            if ((unsigned)yy > 63u) continue;
            #pragma unroll
            for (int dx = 0; dx < 3; ++dx) {
                int xx = x + dx - 1;
                if ((unsigned)xx > 63u) continue;
                acc = fmaf(ip[(yy << 6) + xx], wp[dy * 3 + dx], acc);
            }
        }
    }
    if (do_gelu) acc = 0.5f * acc * (1.f + erff(acc * 0.70710678118654752f));
    out[idx] = acc;
}

// ---------------- patch embed: patches[t][oc] = <pos patch t, embed_w[oc]> + b ----------------
__global__ void k_patch_embed(const float* __restrict__ pos, const float* __restrict__ ew,
                              const float* __restrict__ eb, float* __restrict__ patches) {
    __shared__ float sp[768];
    int b = blockIdx.x, t = b >> 2, qtr = b & 3;
    int hp = t >> 2, wp = t & 3;
    int tid = threadIdx.x;
    for (int i = tid; i < 768; i += 256) {
        int c = i >> 8, r = i & 255, p = r >> 4, q = r & 15;
        sp[i] = pos[(c << 12) + ((hp * 16 + p) << 6) + wp * 16 + q];
    }
    __syncthreads();
    int warp = tid >> 5, lane = tid & 31;
    for (int oi = 0; oi < 24; ++oi) {
        int oc = qtr * 192 + warp * 24 + oi;
        const float* wrow = ew + oc * 768;
        float acc = 0.f;
        #pragma unroll 4
        for (int k = lane; k < 768; k += 32) acc = fmaf(sp[k], wrow[k], acc);
        #pragma unroll
        for (int off = 16; off; off >>= 1) acc += __shfl_down_sync(0xffffffffu, acc, off);
        if (lane == 0) patches[t * 768 + oc] = acc + eb[oc];
    }
}

// ---------------- LN over 768 + QKV gemm. grid 48: (tokgroup 0..3) x (jchunk 0..11) ----------------
__global__ void k_ln_qkv(const float* __restrict__ patches, const float* __restrict__ lg,
                         const float* __restrict__ lb, const float* __restrict__ W,
                         float* __restrict__ qkvp) {
    __shared__ float pn[4 * 772];
    __shared__ float smu[4], srs[4];
    int blk = blockIdx.x;
    int tg = blk / 12, jc = blk % 12;
    int tid = threadIdx.x;
    for (int i = tid; i < 3072; i += 256) {
        int r = i / 768, k = i - r * 768;
        pn[r * 772 + k] = patches[(tg * 4 + r) * 768 + k];
    }
    __syncthreads();
    int warp = tid >> 5, lane = tid & 31;
    if (warp < 4) {
        float s = 0.f, s2 = 0.f;
        for (int k = lane; k < 768; k += 32) {
            float v = pn[warp * 772 + k];
            s += v; s2 = fmaf(v, v, s2);
        }
        #pragma unroll
        for (int off = 16; off; off >>= 1) {
            s  += __shfl_down_sync(0xffffffffu, s, off);
            s2 += __shfl_down_sync(0xffffffffu, s2, off);
        }
        if (lane == 0) {
            float mu = s * (1.f / 768.f);
            float var = s2 * (1.f / 768.f) - mu * mu;
            smu[warp] = mu;
            srs[warp] = rsqrtf(var + LN_EPS);
        }
    }
    __syncthreads();
    for (int i = tid; i < 3072; i += 256) {
        int r = i / 768, k = i - r * 768;
        pn[r * 772 + k] = (pn[r * 772 + k] - smu[r]) * srs[r] * lg[k] + lb[k];
    }
    __syncthreads();
    int tl = tid >> 6, jj = tid & 63;
    int j = jc * 64 + jj;
    const float* pr = pn + tl * 772;
    float acc = 0.f;
    #pragma unroll 4
    for (int k = 0; k < 768; ++k) acc = fmaf(pr[k], W[k * 768 + j], acc);
    qkvp[(tg * 4 + tl) * 768 + j] = acc;
}

// ---------------- patch attention (16 tokens, 8 heads, dh=32) + projection ----------------
__global__ void k_attn_proj(const float* __restrict__ qkvp, const float* __restrict__ pw,
                            const float* __restrict__ pb, float* __restrict__ po) {
    __shared__ float sq[256], sk[16 * 257], sv[16 * 257], ssc[128], sinv[8], sop[256];
    int t = blockIdx.x, tid = threadIdx.x;
    sq[tid] = qkvp[t * 768 + tid];
    for (int i = tid; i < 4096; i += 256) {
        int r = i >> 8, c = i & 255;
        sk[r * 257 + c] = qkvp[r * 768 + 256 + c];
        sv[r * 257 + c] = qkvp[r * 768 + 512 + c];
    }
    __syncthreads();
    if (tid < 128) {
        int h = tid >> 4, j = tid & 15;
        float acc = 0.f;
        #pragma unroll
        for (int d = 0; d < 32; ++d) acc = fmaf(sq[h * 32 + d], sk[j * 257 + h * 32 + d], acc);
        ssc[h * 16 + j] = acc * 0.17677669529663688f;  // 1/sqrt(32)
    }
    __syncthreads();
    if (tid < 8) {
        float mx = -1e30f;
        for (int j = 0; j < 16; ++j) mx = fmaxf(mx, ssc[tid * 16 + j]);
        float s = 0.f;
        for (int j = 0; j < 16; ++j) {
            float e = expf(ssc[tid * 16 + j] - mx);
            ssc[tid * 16 + j] = e;
            s += e;
        }
        sinv[tid] = 1.f / s;
    }
    __syncthreads();
    {
        int h = tid >> 5;
        float acc = 0.f;
        #pragma unroll
        for (int j = 0; j < 16; ++j) acc = fmaf(ssc[h * 16 + j], sv[j * 257 + tid], acc);
        sop[tid] = acc * sinv[h];
    }
    __syncthreads();
    #pragma unroll
    for (int r = 0; r < 3; ++r) {
        int m = r * 256 + tid;
        float acc = 0.f;
        #pragma unroll 4
        for (int d = 0; d < 256; ++d) acc = fmaf(sop[d], pw[d * 768 + m], acc);
        po[t * 768 + m] = acc + pb[m];
    }
}

// ---------------- reconstruction (ConvTranspose k=s=16) -> comb = out_patch ----------------
__global__ void k_recon(const float* __restrict__ po, const float* __restrict__ rw,
                        const float* __restrict__ rb, float* __restrict__ comb) {
    __shared__ float spo[4 * 772];
    int idx = blockIdx.x * 256 + threadIdx.x;
    int c = idx >> 12, rem = idx & 4095, y = rem >> 6, x = rem & 63;
    int hp = y >> 4, iy = y & 15, wp = x >> 4, jx = x & 15;
    int tid = threadIdx.x;
    for (int i = tid; i < 3072; i += 256) {
        int r = i / 768, k = i - r * 768;
        spo[r * 772 + k] = po[(hp * 4 + r) * 768 + k];
    }
    __syncthreads();
    const float* pr = spo + wp * 772;
    int wbase = c * 256 + iy * 16 + jx;
    float acc = 0.f;
    #pragma unroll 4
    for (int ch = 0; ch < 768; ++ch) acc = fmaf(pr[ch], rw[ch * 768 + wbase], acc);
    comb[idx] = acc + rb[c];
}

// ---------------- moments of LN'd pixel features (deg<=4) + per-head 3x3 maps ----------------
__global__ void __launch_bounds__(512) k_moments(
        const float* __restrict__ pos, const float* __restrict__ g2,
        const float* __restrict__ b2, const float* __restrict__ Wseq,
        const float* __restrict__ Pseq, Scratch* S) {
    __shared__ float part[16 * 35];
    __shared__ float smom[35];
    int tid = threadIdx.x, warp = tid >> 5, lane = tid & 31;
    float acc[35];
    #pragma unroll
    for (int m = 0; m < 35; ++m) acc[m] = 0.f;
    float G0 = g2[0], G1 = g2[1], G2 = g2[2];
    float B0 = b2[0], B1 = b2[1], B2 = b2[2];
    for (int rep = 0; rep < 8; ++rep) {
        int i = tid + rep * 512;
        float p0 = pos[i], p1 = pos[4096 + i], p2 = pos[8192 + i];
        float mu = (p0 + p1 + p2) * (1.f / 3.f);
        float d0 = p0 - mu, d1 = p1 - mu, d2 = p2 - mu;
        float rs = rsqrtf((d0 * d0 + d1 * d1 + d2 * d2) * (1.f / 3.f) + LN_EPS);
        float s0 = d0 * rs * G0 + B0, s1 = d1 * rs * G1 + B1, s2 = d2 * rs * G2 + B2;
        float mo[35];
        mon35(s0, s1, s2, mo);
        #pragma unroll
        for (int m = 0; m < 35; ++m) acc[m] += mo[m];
    }
    #pragma unroll
    for (int m = 0; m < 35; ++m) {
        #pragma unroll
        for (int off = 16; off; off >>= 1) acc[m] += __shfl_down_sync(0xffffffffu, acc[m], off);
    }
    if (lane == 0) {
        for (int m = 0; m < 35; ++m) part[warp * 35 + m] = acc[m];
    }
    __syncthreads();
    if (tid < 35) {
        float t = 0.f;
        for (int w2 = 0; w2 < 16; ++w2) t += part[w2 * 35 + tid];
        smom[tid] = t;
    }
    __syncthreads();
    if (tid < 20) S->cden[tid] = smom[tid] * c_invfact[tid];
    if (tid >= 32 && tid < 92) {
        int q = tid - 32;
        S->cnum[q] = smom[c_plus[q]] * c_invfact[q % 20];
    }
    if (tid >= 128 && tid < 200) {
        int q = tid - 128;
        int h = q / 9, rr = q % 9, qq = rr / 3, pp = rr % 3;
        float a = 0.f;
        for (int d = 0; d < 32; ++d)
            a = fmaf(Wseq[qq * 768 + 256 + h * 32 + d], Wseq[pp * 768 + h * 32 + d], a);
        S->A[q] = a * 0.17677669529663688f;  // /sqrt(32)
    }
    if (tid >= 256 && tid < 328) {
        int q = tid - 256;
        int h = q / 9, rr = q % 9, pp = rr / 3, cc = rr % 3;
        float a = 0.f;
        for (int d = 0; d < 32; ++d)
            a = fmaf(Wseq[pp * 768 + 512 + h * 32 + d], Pseq[(h * 32 + d) * 3 + cc], a);
        S->C[q] = a;
    }
}

// ---------------- pixel attention via moment polynomials, comb += out_seq ----------------
__global__ void k_seq_attn(const float* __restrict__ pos, const float* __restrict__ g2,
                           const float* __restrict__ b2, const float* __restrict__ psb,
                           const Scratch* __restrict__ S, float* __restrict__ comb) {
    __shared__ float sA[72], sC[72], scd[20], scn[60];
    int tid = threadIdx.x;
    if (tid < 72) { sA[tid] = S->A[tid]; sC[tid] = S->C[tid]; }
    if (tid >= 128 && tid < 148) scd[tid - 128] = S->cden[tid - 128];
    if (tid >= 160 && tid < 220) scn[tid - 160] = S->cnum[tid - 160];
    __syncthreads();
    int i = blockIdx.x * 256 + tid;
    float p0 = pos[i], p1 = pos[4096 + i], p2 = pos[8192 + i];
    float mu = (p0 + p1 + p2) * (1.f / 3.f);
    float d0 = p0 - mu, d1 = p1 - mu, d2 = p2 - mu;
    float rs = rsqrtf((d0 * d0 + d1 * d1 + d2 * d2) * (1.f / 3.f) + LN_EPS);
    float s0 = d0 * rs * g2[0] + b2[0];
    float s1 = d1 * rs * g2[1] + b2[1];
    float s2 = d2 * rs * g2[2] + b2[2];
    float o0 = 0.f, o1 = 0.f, o2 = 0.f;
    #pragma unroll
    for (int h = 0; h < 8; ++h) {
        const float* Ah = sA + h * 9;
        float a0 = Ah[0] * s0 + Ah[1] * s1 + Ah[2] * s2;
        float a1 = Ah[3] * s0 + Ah[4] * s1 + Ah[5] * s2;
        float a2 = Ah[6] * s0 + Ah[7] * s1 + Ah[8] * s2;
        float m[20];
        m[0]=1.f; m[1]=a0; m[2]=a1; m[3]=a2;
        m[4]=a0*a0; m[5]=a0*a1; m[6]=a0*a2; m[7]=a1*a1; m[8]=a1*a2; m[9]=a2*a2;
        m[10]=m[4]*a0; m[11]=m[4]*a1; m[12]=m[4]*a2; m[13]=a0*m[7]; m[14]=m[5]*a2;
        m[15]=a0*m[9]; m[16]=m[7]*a1; m[17]=m[7]*a2; m[18]=a1*m[9]; m[19]=m[9]*a2;
        float den = 0.f, n0 = 0.f, n1 = 0.f, n2 = 0.f;
        #pragma unroll
        for (int q = 0; q < 20; ++q) {
            den = fmaf(scd[q],      m[q], den);
            n0  = fmaf(scn[q],      m[q], n0);
            n1  = fmaf(scn[20 + q], m[q], n1);
            n2  = fmaf(scn[40 + q], m[q], n2);
        }
        float rinv = 1.f / den;
        float r0 = n0 * rinv, r1 = n1 * rinv, r2 = n2 * rinv;
        const float* Ch = sC + h * 9;
        o0 += r0 * Ch[0] + r1 * Ch[3] + r2 * Ch[6];
        o1 += r0 * Ch[1] + r1 * Ch[4] + r2 * Ch[7];
        o2 += r0 * Ch[2] + r1 * Ch[5] + r2 * Ch[8];
    }
    comb[i]         += o0 + psb[0];
    comb[4096 + i]  += o1 + psb[1];
    comb[8192 + i]  += o2 + psb[2];
}

// ---------------- launch ----------------
extern "C" void kernel_launch(void* const* d_in, const int* in_sizes, int n_in,
                              void* d_out, int out_size) {
    const float* x    = (const float*)d_in[0];
    const float* pew1 = (const float*)d_in[1];
    const float* pew2 = (const float*)d_in[2];
    const float* ew   = (const float*)d_in[3];
    const float* eb   = (const float*)d_in[4];
    const float* l1g  = (const float*)d_in[5];
    const float* l1b  = (const float*)d_in[6];
    const float* qpw  = (const float*)d_in[7];
    const float* ppw  = (const float*)d_in[8];
    const float* ppb  = (const float*)d_in[9];
    const float* rw   = (const float*)d_in[10];
    const float* rb   = (const float*)d_in[11];
    const float* l2g  = (const float*)d_in[12];
    const float* l2b  = (const float*)d_in[13];
    const float* qsw  = (const float*)d_in[14];
    const float* psw  = (const float*)d_in[15];
    const float* psb  = (const float*)d_in[16];
    const float* pdw1 = (const float*)d_in[17];
    const float* pdw2 = (const float*)d_in[18];
    float* out = (float*)d_out;

    Scratch* S = nullptr;
    cudaGetSymbolAddress((void**)&S, g_s);

    k_conv3<<<48, 256>>>(x, pew1, S->t1, 1);
    k_conv3<<<48, 256>>>(S->t1, pew2, S->pos, 0);
    k_patch_embed<<<64, 256>>>(S->pos, ew, eb, S->patches);
    k_ln_qkv<<<48, 256>>>(S->patches, l1g, l1b, qpw, S->qkvp);
    k_attn_proj<<<16, 256>>>(S->qkvp, ppw, ppb, S->po);
    k_recon<<<48, 256>>>(S->po, rw, rb, S->comb);
    k_moments<<<1, 512>>>(S->pos, l2g, l2b, qsw, psw, S);
    k_seq_attn<<<16, 256>>>(S->pos, l2g, l2b, psb, S, S->comb);
    k_conv3<<<48, 256>>>(S->comb, pdw1, S->t2, 1);
    k_conv3<<<48, 256>>>(S->t2, pdw2, out, 0);
}

// round 2
// speedup vs baseline: 1.7616x; 1.7616x over previous
#include <cuda_runtime.h>
#include <math.h>

#define LN_EPS 1e-5f

// ---------------- scratch (no allocation allowed) ----------------
struct Scratch {
    float t1[12288];          // gelu(conv1(x))
    float pos[12288];         // conv2(...)
    float patches[16 * 768];  // patch embed
    float qkvp[16 * 768];     // patch qkv
    float sop[16 * 256];      // attention output per token (pre-projection)
    float po[16 * 768];       // attn+proj output per token
    float comb[12288];        // out_patch then += out_seq
    float t2[12288];          // gelu(conv3(comb))
    float cden[20];           // moment-derived denominator coeffs
    float cnum[60];           // numerator coeffs (3 x 20)
    float A[72];              // per-head 3x3 score maps
    float C[72];              // per-head 3x3 value*proj maps
};
__device__ Scratch g_s;

// 1/(i! j! l!) for the 20 monomials of degree <= 3 (ordering below)
__device__ const float c_invfact[20] = {
    1.f, 1.f, 1.f, 1.f,
    0.5f, 1.f, 1.f, 0.5f, 1.f, 0.5f,
    1.f/6.f, 0.5f, 0.5f, 0.5f, 1.f, 0.5f, 1.f/6.f, 0.5f, 0.5f, 1.f/6.f
};
// index of monomial m (deg<=3) with exponent of variable c incremented (deg<=4 table)
__device__ const int c_plus[60] = {
    1,4,5,6,10,11,12,13,14,15,20,21,22,23,24,25,26,27,28,29,
    2,5,7,8,11,13,14,16,17,18,21,23,24,26,27,28,30,31,32,33,
    3,6,8,9,12,14,15,17,18,19,22,24,25,27,28,29,31,32,33,34
};

// monomials of (s0,s1,s2) up to degree 4 (35 values)
__device__ __forceinline__ void mon35(float s0, float s1, float s2, float* m) {
    m[0]=1.f; m[1]=s0; m[2]=s1; m[3]=s2;
    m[4]=s0*s0; m[5]=s0*s1; m[6]=s0*s2; m[7]=s1*s1; m[8]=s1*s2; m[9]=s2*s2;
    m[10]=m[4]*s0; m[11]=m[4]*s1; m[12]=m[4]*s2; m[13]=s0*m[7]; m[14]=m[5]*s2;
    m[15]=s0*m[9]; m[16]=m[7]*s1; m[17]=m[7]*s2; m[18]=s1*m[9]; m[19]=m[9]*s2;
    m[20]=m[10]*s0; m[21]=m[10]*s1; m[22]=m[10]*s2; m[23]=m[11]*s1; m[24]=m[11]*s2;
    m[25]=m[12]*s2; m[26]=m[16]*s0; m[27]=m[13]*s2; m[28]=m[14]*s2; m[29]=m[19]*s0;
    m[30]=m[16]*s1; m[31]=m[16]*s2; m[32]=m[17]*s2; m[33]=m[19]*s1; m[34]=m[19]*s2;
}

// ---------------- 3x3 conv, pad 1, 3 channels in/out, optional exact gelu ----------------
__global__ void __launch_bounds__(256) k_conv3(const float* __restrict__ in,
                                               const float* __restrict__ w,
                                               float* __restrict__ out, int do_gelu) {
    int idx = blockIdx.x * blockDim.x + threadIdx.x;
    int o = idx >> 12, rem = idx & 4095, y = rem >> 6, x = rem & 63;
    float acc = 0.f;
    #pragma unroll
    for (int c = 0; c < 3; ++c) {
        const float* wp = w + (o * 3 + c) * 9;
        const float* ip = in + (c << 12);
        float w00=wp[0],w01=wp[1],w02=wp[2],w10=wp[3],w11=wp[4],w12=wp[5],w20=wp[6],w21=wp[7],w22=wp[8];
        #pragma unroll
        for (int dy = 0; dy < 3; ++dy) {
            int yy = y + dy - 1;
            if ((unsigned)yy > 63u) continue;
            float wr0 = dy==0?w00:(dy==1?w10:w20);
            float wr1 = dy==0?w01:(dy==1?w11:w21);
            float wr2 = dy==0?w02:(dy==1?w12:w22);
            const float* row = ip + (yy << 6);
            if (x > 0)  acc = fmaf(row[x - 1], wr0, acc);
            acc = fmaf(row[x], wr1, acc);
            if (x < 63) acc = fmaf(row[x + 1], wr2, acc);
        }
    }
    if (do_gelu) acc = 0.5f * acc * (1.f + erff(acc * 0.70710678118654752f));
    out[idx] = acc;
}

// ---------------- patch embed: warp computes 4 output channels for one token ----------------
// grid 384, block 256 (8 warps). 3072 warps total = 16 tokens * 192 groups of 4 oc.
__global__ void __launch_bounds__(256) k_patch_embed(const float* __restrict__ pos,
                                                     const float* __restrict__ ew,
                                                     const float* __restrict__ eb,
                                                     float* __restrict__ patches) {
    int gw = blockIdx.x * 8 + (threadIdx.x >> 5);
    int lane = threadIdx.x & 31;
    int t = gw / 192;
    int ocb = (gw - t * 192) * 4;
    int hp = t >> 2, wp = t & 3;
    float a0 = 0.f, a1 = 0.f, a2 = 0.f, a3 = 0.f;
    const float* e0 = ew + (ocb + 0) * 768;
    const float* e1 = ew + (ocb + 1) * 768;
    const float* e2 = ew + (ocb + 2) * 768;
    const float* e3 = ew + (ocb + 3) * 768;
    #pragma unroll 4
    for (int i = 0; i < 24; ++i) {
        int k = i * 32 + lane;
        int c = k >> 8, r = k & 255, p = r >> 4, q = r & 15;
        float xv = pos[(c << 12) + ((hp * 16 + p) << 6) + wp * 16 + q];
        a0 = fmaf(xv, e0[k], a0);
        a1 = fmaf(xv, e1[k], a1);
        a2 = fmaf(xv, e2[k], a2);
        a3 = fmaf(xv, e3[k], a3);
    }
    #pragma unroll
    for (int off = 16; off; off >>= 1) {
        a0 += __shfl_down_sync(0xffffffffu, a0, off);
        a1 += __shfl_down_sync(0xffffffffu, a1, off);
        a2 += __shfl_down_sync(0xffffffffu, a2, off);
        a3 += __shfl_down_sync(0xffffffffu, a3, off);
    }
    if (lane == 0) {
        patches[t * 768 + ocb + 0] = a0 + eb[ocb + 0];
        patches[t * 768 + ocb + 1] = a1 + eb[ocb + 1];
        patches[t * 768 + ocb + 2] = a2 + eb[ocb + 2];
        patches[t * 768 + ocb + 3] = a3 + eb[ocb + 3];
    }
}

// ---------------- LN over 768 + QKV gemm ----------------
// grid 24 = (4 token groups) x (6 j chunks of 128). block 256: half = 2 tokens each.
__global__ void __launch_bounds__(256) k_ln_qkv(const float* __restrict__ patches,
                                                const float* __restrict__ lg,
                                                const float* __restrict__ lb,
                                                const float* __restrict__ W,
                                                float* __restrict__ qkvp) {
    __shared__ float pn[4 * 768];
    __shared__ float smu[4], srs[4];
    int tg = blockIdx.x / 6, jc = blockIdx.x % 6;
    int tid = threadIdx.x;
    for (int i = tid; i < 3072; i += 256)
        pn[i] = patches[tg * 3072 + i];
    __syncthreads();
    int warp = tid >> 5, lane = tid & 31;
    if (warp < 4) {
        float s = 0.f, s2 = 0.f;
        for (int k = lane; k < 768; k += 32) {
            float v = pn[warp * 768 + k];
            s += v; s2 = fmaf(v, v, s2);
        }
        #pragma unroll
        for (int off = 16; off; off >>= 1) {
            s  += __shfl_down_sync(0xffffffffu, s, off);
            s2 += __shfl_down_sync(0xffffffffu, s2, off);
        }
        if (lane == 0) {
            float mu = s * (1.f / 768.f);
            float var = s2 * (1.f / 768.f) - mu * mu;
            smu[warp] = mu;
            srs[warp] = rsqrtf(var + LN_EPS);
        }
    }
    __syncthreads();
    for (int i = tid; i < 3072; i += 256) {
        int r = i / 768, k = i - r * 768;
        pn[i] = (pn[i] - smu[r]) * srs[r] * lg[k] + lb[k];
    }
    __syncthreads();
    int half = tid >> 7, jj = tid & 127;
    int j = jc * 128 + jj;
    int t0 = half * 2;
    const float4* A0 = (const float4*)(pn + t0 * 768);
    const float4* A1 = (const float4*)(pn + (t0 + 1) * 768);
    float acc0 = 0.f, acc1 = 0.f;
    const float* Wj = W + j;
    #pragma unroll 2
    for (int kk = 0; kk < 192; ++kk) {
        float4 a0 = A0[kk], a1 = A1[kk];
        float w0 = Wj[(kk * 4 + 0) * 768];
        float w1 = Wj[(kk * 4 + 1) * 768];
        float w2 = Wj[(kk * 4 + 2) * 768];
        float w3 = Wj[(kk * 4 + 3) * 768];
        acc0 = fmaf(a0.x, w0, acc0); acc1 = fmaf(a1.x, w0, acc1);
        acc0 = fmaf(a0.y, w1, acc0); acc1 = fmaf(a1.y, w1, acc1);
        acc0 = fmaf(a0.z, w2, acc0); acc1 = fmaf(a1.z, w2, acc1);
        acc0 = fmaf(a0.w, w3, acc0); acc1 = fmaf(a1.w, w3, acc1);
    }
    qkvp[(tg * 4 + t0) * 768 + j] = acc0;
    qkvp[(tg * 4 + t0 + 1) * 768 + j] = acc1;
}

// ---------------- patch attention (16 tokens, 8 heads, dh=32) + projection ----------------
__global__ void __launch_bounds__(256) k_attn_proj(const float* __restrict__ qkvp,
                                                   const float* __restrict__ pw,
                                                   const float* __restrict__ pb,
                                                   float* __restrict__ po) {
    __shared__ float sq[256], sk[16 * 257], sv[16 * 257], ssc[128], sinv[8], sop[256];
    int t = blockIdx.x, tid = threadIdx.x;
    sq[tid] = qkvp[t * 768 + tid];
    for (int i = tid; i < 4096; i += 256) {
        int r = i >> 8, c = i & 255;
        sk[r * 257 + c] = qkvp[r * 768 + 256 + c];
        sv[r * 257 + c] = qkvp[r * 768 + 512 + c];
    }
    __syncthreads();
    if (tid < 128) {
        int h = tid >> 4, j = tid & 15;
        float acc = 0.f;
        #pragma unroll
        for (int d = 0; d < 32; ++d) acc = fmaf(sq[h * 32 + d], sk[j * 257 + h * 32 + d], acc);
        ssc[h * 16 + j] = acc * 0.17677669529663688f;  // 1/sqrt(32)
    }
    __syncthreads();
    if (tid < 8) {
        float mx = -1e30f;
        for (int j = 0; j < 16; ++j) mx = fmaxf(mx, ssc[tid * 16 + j]);
        float s = 0.f;
        for (int j = 0; j < 16; ++j) {
            float e = expf(ssc[tid * 16 + j] - mx);
            ssc[tid * 16 + j] = e;
            s += e;
        }
        sinv[tid] = 1.f / s;
    }
    __syncthreads();
    {
        int h = tid >> 5;
        float acc = 0.f;
        #pragma unroll
        for (int j = 0; j < 16; ++j) acc = fmaf(ssc[h * 16 + j], sv[j * 257 + tid], acc);
        sop[tid] = acc * sinv[h];
    }
    __syncthreads();
    // projection: 3 interleaved accumulators, float4 smem reads
    float acc0 = 0.f, acc1 = 0.f, acc2 = 0.f;
    const float4* s4 = (const float4*)sop;
    const float* pw0 = pw + tid;
    const float* pw1 = pw + 256 + tid;
    const float* pw2 = pw + 512 + tid;
    #pragma unroll 2
    for (int dd = 0; dd < 64; ++dd) {
        float4 sv4 = s4[dd];
        int d = dd * 4;
        acc0 = fmaf(sv4.x, pw0[(d + 0) * 768], acc0);
        acc1 = fmaf(sv4.x, pw1[(d + 0) * 768], acc1);
        acc2 = fmaf(sv4.x, pw2[(d + 0) * 768], acc2);
        acc0 = fmaf(sv4.y, pw0[(d + 1) * 768], acc0);
        acc1 = fmaf(sv4.y, pw1[(d + 1) * 768], acc1);
        acc2 = fmaf(sv4.y, pw2[(d + 1) * 768], acc2);
        acc0 = fmaf(sv4.z, pw0[(d + 2) * 768], acc0);
        acc1 = fmaf(sv4.z, pw1[(d + 2) * 768], acc1);
        acc2 = fmaf(sv4.z, pw2[(d + 2) * 768], acc2);
        acc0 = fmaf(sv4.w, pw0[(d + 3) * 768], acc0);
        acc1 = fmaf(sv4.w, pw1[(d + 3) * 768], acc1);
        acc2 = fmaf(sv4.w, pw2[(d + 3) * 768], acc2);
    }
    po[t * 768 + tid]       = acc0 + pb[tid];
    po[t * 768 + 256 + tid] = acc1 + pb[256 + tid];
    po[t * 768 + 512 + tid] = acc2 + pb[512 + tid];
}

// ---------------- reconstruction gemm: comb = scatter(po @ rw) + rb ----------------
// grid 24 = (4 token groups) x (6 j chunks of 128). block 256, half = 2 tokens each.
__global__ void __launch_bounds__(256) k_recon(const float* __restrict__ po,
                                               const float* __restrict__ rw,
                                               const float* __restrict__ rb,
                                               float* __restrict__ comb) {
    __shared__ float sp[4 * 768];
    int tg = blockIdx.x / 6, jc = blockIdx.x % 6;
    int tid = threadIdx.x;
    for (int i = tid; i < 3072; i += 256)
        sp[i] = po[tg * 3072 + i];
    __syncthreads();
    int half = tid >> 7, jj = tid & 127;
    int j = jc * 128 + jj;
    int t0 = half * 2;
    const float4* A0 = (const float4*)(sp + t0 * 768);
    const float4* A1 = (const float4*)(sp + (t0 + 1) * 768);
    float acc0 = 0.f, acc1 = 0.f;
    const float* Wj = rw + j;
    #pragma unroll 2
    for (int kk = 0; kk < 192; ++kk) {
        float4 a0 = A0[kk], a1 = A1[kk];
        float w0 = Wj[(kk * 4 + 0) * 768];
        float w1 = Wj[(kk * 4 + 1) * 768];
        float w2 = Wj[(kk * 4 + 2) * 768];
        float w3 = Wj[(kk * 4 + 3) * 768];
        acc0 = fmaf(a0.x, w0, acc0); acc1 = fmaf(a1.x, w0, acc1);
        acc0 = fmaf(a0.y, w1, acc0); acc1 = fmaf(a1.y, w1, acc1);
        acc0 = fmaf(a0.z, w2, acc0); acc1 = fmaf(a1.z, w2, acc1);
        acc0 = fmaf(a0.w, w3, acc0); acc1 = fmaf(a1.w, w3, acc1);
    }
    int c = j >> 8, r = j & 255, iy = r >> 4, jx = r & 15;
    float bias = rb[c];
    #pragma unroll
    for (int tt = 0; tt < 2; ++tt) {
        int t = tg * 4 + t0 + tt;
        int hp = t >> 2, wp = t & 3;
        float a = tt == 0 ? acc0 : acc1;
        comb[(c << 12) + ((hp * 16 + iy) << 6) + wp * 16 + jx] = a + bias;
    }
}

// ---------------- moments of LN'd pixel features (deg<=4) + per-head 3x3 maps ----------------
__global__ void __launch_bounds__(512) k_moments(
        const float* __restrict__ pos, const float* __restrict__ g2,
        const float* __restrict__ b2, const float* __restrict__ Wseq,
        const float* __restrict__ Pseq, Scratch* S) {
    __shared__ float part[16 * 35];
    __shared__ float smom[35];
    int tid = threadIdx.x, warp = tid >> 5, lane = tid & 31;
    float acc[35];
    #pragma unroll
    for (int m = 0; m < 35; ++m) acc[m] = 0.f;
    float G0 = g2[0], G1 = g2[1], G2 = g2[2];
    float B0 = b2[0], B1 = b2[1], B2 = b2[2];
    for (int rep = 0; rep < 8; ++rep) {
        int i = tid + rep * 512;
        float p0 = pos[i], p1 = pos[4096 + i], p2 = pos[8192 + i];
        float mu = (p0 + p1 + p2) * (1.f / 3.f);
        float d0 = p0 - mu, d1 = p1 - mu, d2 = p2 - mu;
        float rs = rsqrtf((d0 * d0 + d1 * d1 + d2 * d2) * (1.f / 3.f) + LN_EPS);
        float s0 = d0 * rs * G0 + B0, s1 = d1 * rs * G1 + B1, s2 = d2 * rs * G2 + B2;
        float mo[35];
        mon35(s0, s1, s2, mo);
        #pragma unroll
        for (int m = 0; m < 35; ++m) acc[m] += mo[m];
    }
    #pragma unroll
    for (int m = 0; m < 35; ++m) {
        #pragma unroll
        for (int off = 16; off; off >>= 1) acc[m] += __shfl_down_sync(0xffffffffu, acc[m], off);
    }
    if (lane == 0) {
        for (int m = 0; m < 35; ++m) part[warp * 35 + m] = acc[m];
    }
    __syncthreads();
    if (tid < 35) {
        float t = 0.f;
        for (int w2 = 0; w2 < 16; ++w2) t += part[w2 * 35 + tid];
        smom[tid] = t;
    }
    __syncthreads();
    if (tid < 20) S->cden[tid] = smom[tid] * c_invfact[tid];
    if (tid >= 32 && tid < 92) {
        int q = tid - 32;
        S->cnum[q] = smom[c_plus[q]] * c_invfact[q % 20];
    }
    if (tid >= 128 && tid < 200) {
        int q = tid - 128;
        int h = q / 9, rr = q % 9, qq = rr / 3, pp = rr % 3;
        float a = 0.f;
        for (int d = 0; d < 32; ++d)
            a = fmaf(Wseq[qq * 768 + 256 + h * 32 + d], Wseq[pp * 768 + h * 32 + d], a);
        S->A[q] = a * 0.17677669529663688f;  // /sqrt(32)
    }
    if (tid >= 256 && tid < 328) {
        int q = tid - 256;
        int h = q / 9, rr = q % 9, pp = rr / 3, cc = rr % 3;
        float a = 0.f;
        for (int d = 0; d < 32; ++d)
            a = fmaf(Wseq[pp * 768 + 512 + h * 32 + d], Pseq[(h * 32 + d) * 3 + cc], a);
        S->C[q] = a;
    }
}

// ---------------- pixel attention via moment polynomials, comb += out_seq ----------------
__global__ void __launch_bounds__(256) k_seq_attn(const float* __restrict__ pos,
                                                  const float* __restrict__ g2,
                                                  const float* __restrict__ b2,
                                                  const float* __restrict__ psb,
                                                  const Scratch* __restrict__ S,
                                                  float* __restrict__ comb) {
    __shared__ float sA[72], sC[72], scd[20], scn[60];
    int tid = threadIdx.x;
    if (tid < 72) { sA[tid] = S->A[tid]; sC[tid] = S->C[tid]; }
    if (tid >= 128 && tid < 148) scd[tid - 128] = S->cden[tid - 128];
    if (tid >= 160 && tid < 220) scn[tid - 160] = S->cnum[tid - 160];
    __syncthreads();
    int i = blockIdx.x * 256 + tid;
    float p0 = pos[i], p1 = pos[4096 + i], p2 = pos[8192 + i];
    float mu = (p0 + p1 + p2) * (1.f / 3.f);
    float d0 = p0 - mu, d1 = p1 - mu, d2 = p2 - mu;
    float rs = rsqrtf((d0 * d0 + d1 * d1 + d2 * d2) * (1.f / 3.f) + LN_EPS);
    float s0 = d0 * rs * g2[0] + b2[0];
    float s1 = d1 * rs * g2[1] + b2[1];
    float s2 = d2 * rs * g2[2] + b2[2];
    float o0 = 0.f, o1 = 0.f, o2 = 0.f;
    #pragma unroll
    for (int h = 0; h < 8; ++h) {
        const float* Ah = sA + h * 9;
        float a0 = Ah[0] * s0 + Ah[1] * s1 + Ah[2] * s2;
        float a1 = Ah[3] * s0 + Ah[4] * s1 + Ah[5] * s2;
        float a2 = Ah[6] * s0 + Ah[7] * s1 + Ah[8] * s2;
        float m[20];
        m[0]=1.f; m[1]=a0; m[2]=a1; m[3]=a2;
        m[4]=a0*a0; m[5]=a0*a1; m[6]=a0*a2; m[7]=a1*a1; m[8]=a1*a2; m[9]=a2*a2;
        m[10]=m[4]*a0; m[11]=m[4]*a1; m[12]=m[4]*a2; m[13]=a0*m[7]; m[14]=m[5]*a2;
        m[15]=a0*m[9]; m[16]=m[7]*a1; m[17]=m[7]*a2; m[18]=a1*m[9]; m[19]=m[9]*a2;
        float den = 0.f, n0 = 0.f, n1 = 0.f, n2 = 0.f;
        #pragma unroll
        for (int q = 0; q < 20; ++q) {
            den = fmaf(scd[q],      m[q], den);
            n0  = fmaf(scn[q],      m[q], n0);
            n1  = fmaf(scn[20 + q], m[q], n1);
            n2  = fmaf(scn[40 + q], m[q], n2);
        }
        float rinv = 1.f / den;
        float r0 = n0 * rinv, r1 = n1 * rinv, r2 = n2 * rinv;
        const float* Ch = sC + h * 9;
        o0 += r0 * Ch[0] + r1 * Ch[3] + r2 * Ch[6];
        o1 += r0 * Ch[1] + r1 * Ch[4] + r2 * Ch[7];
        o2 += r0 * Ch[2] + r1 * Ch[5] + r2 * Ch[8];
    }
    comb[i]         += o0 + psb[0];
    comb[4096 + i]  += o1 + psb[1];
    comb[8192 + i]  += o2 + psb[2];
}

// ---------------- launch ----------------
extern "C" void kernel_launch(void* const* d_in, const int* in_sizes, int n_in,
                              void* d_out, int out_size) {
    const float* x    = (const float*)d_in[0];
    const float* pew1 = (const float*)d_in[1];
    const float* pew2 = (const float*)d_in[2];
    const float* ew   = (const float*)d_in[3];
    const float* eb   = (const float*)d_in[4];
    const float* l1g  = (const float*)d_in[5];
    const float* l1b  = (const float*)d_in[6];
    const float* qpw  = (const float*)d_in[7];
    const float* ppw  = (const float*)d_in[8];
    const float* ppb  = (const float*)d_in[9];
    const float* rw   = (const float*)d_in[10];
    const float* rb   = (const float*)d_in[11];
    const float* l2g  = (const float*)d_in[12];
    const float* l2b  = (const float*)d_in[13];
    const float* qsw  = (const float*)d_in[14];
    const float* psw  = (const float*)d_in[15];
    const float* psb  = (const float*)d_in[16];
    const float* pdw1 = (const float*)d_in[17];
    const float* pdw2 = (const float*)d_in[18];
    float* out = (float*)d_out;

    Scratch* S = nullptr;
    cudaGetSymbolAddress((void**)&S, g_s);

    k_conv3<<<48, 256>>>(x, pew1, S->t1, 1);
    k_conv3<<<48, 256>>>(S->t1, pew2, S->pos, 0);
    k_patch_embed<<<384, 256>>>(S->pos, ew, eb, S->patches);
    k_ln_qkv<<<24, 256>>>(S->patches, l1g, l1b, qpw, S->qkvp);
    k_attn_proj<<<16, 256>>>(S->qkvp, ppw, ppb, S->po);
    k_recon<<<24, 256>>>(S->po, rw, rb, S->comb);
    k_moments<<<1, 512>>>(S->pos, l2g, l2b, qsw, psw, S);
    k_seq_attn<<<16, 256>>>(S->pos, l2g, l2b, psb, S, S->comb);
    k_conv3<<<48, 256>>>(S->comb, pdw1, S->t2, 1);
    k_conv3<<<48, 256>>>(S->t2, pdw2, out, 0);
}